// round 5
// baseline (speedup 1.0000x reference)
#include <cuda_runtime.h>

// Problem constants (fixed by the reference)
#define BATCH   8
#define CHN     512
#define HH      56
#define WWD     56
#define HWSZ    3136            // 56*56
#define NHEADS  16
#define DHEAD   32
#define KS      7
#define NTOK    (BATCH*HWSZ)    // 25088

// Scratch: channel-major [b][c][hw] buffers (allocation-free per harness rules)
__device__ float g_q[BATCH*CHN*HWSZ];
__device__ float g_k[BATCH*CHN*HWSZ];
__device__ float g_v[BATCH*CHN*HWSZ];
__device__ float g_o[BATCH*CHN*HWSZ];

// ---------------------------------------------------------------------------
// GEMM: C[m][tok] = sum_k A[m][k] * B[k][tok]
//   A: MxK row-major weights (K=512 contiguous)
//   B: channel-major activations [b][k][hw]  (tok = b*3136 + hw)
// MODE 0: A=qkv_w (M=1536), B=x, epilogue splits into g_q (scaled)/g_k/g_v
// MODE 1: A=proj_w (M=512), B=g_o, epilogue adds bias, writes NCHW output
// ---------------------------------------------------------------------------
template<int MODE>
__global__ __launch_bounds__(256, 2)
void gemm_ct(const float* __restrict__ A,
             const float* __restrict__ Bx,
             const float* __restrict__ bias,
             float* __restrict__ Cout)
{
    constexpr int BM = 128, BN = 128, BK = 16, TM = 8, TN = 8;
    __shared__ __align__(16) float As[BK][BM + 4];
    __shared__ __align__(16) float Bs[BK][BN + 4];

    const int tid = threadIdx.x;
    const int tx  = tid & 15;        // 16 N-threads
    const int ty  = tid >> 4;        // 16 M-threads
    const int m0  = blockIdx.y * BM;
    const int n0  = blockIdx.x * BN;

    const float* Bp = (MODE == 0) ? Bx : (const float*)g_o;

    // B loader: each thread owns one token column, 8 k-rows per tile
    const int tokl = tid & 127;
    const int tok  = n0 + tokl;
    const int bb   = tok / HWSZ;
    const int bhw  = tok - bb * HWSZ;
    const float* bptr = Bp + bb * (CHN * HWSZ) + bhw;
    const int bk0 = tid >> 7;        // 0 or 1

    // A loader: 128 rows x 16 k per tile -> 2 float4 per thread along K
    const int arow = tid >> 1;
    const int akq  = (tid & 1) << 3; // 0 or 8
    const float* aptr = A + (m0 + arow) * CHN + akq;

    float acc[TM][TN];
#pragma unroll
    for (int i = 0; i < TM; i++)
#pragma unroll
        for (int j = 0; j < TN; j++) acc[i][j] = 0.f;

    for (int k0 = 0; k0 < CHN; k0 += BK) {
        float4 a0 = *(const float4*)(aptr + k0);
        float4 a1 = *(const float4*)(aptr + k0 + 4);
        As[akq + 0][arow] = a0.x;  As[akq + 1][arow] = a0.y;
        As[akq + 2][arow] = a0.z;  As[akq + 3][arow] = a0.w;
        As[akq + 4][arow] = a1.x;  As[akq + 5][arow] = a1.y;
        As[akq + 6][arow] = a1.z;  As[akq + 7][arow] = a1.w;
#pragma unroll
        for (int p = 0; p < 8; p++) {
            const int kr = p * 2 + bk0;
            Bs[kr][tokl] = bptr[(k0 + kr) * HWSZ];
        }
        __syncthreads();
#pragma unroll
        for (int kk = 0; kk < BK; kk++) {
            float ar[TM], br[TN];
            *(float4*)&ar[0] = *(const float4*)&As[kk][ty * TM];
            *(float4*)&ar[4] = *(const float4*)&As[kk][ty * TM + 4];
            *(float4*)&br[0] = *(const float4*)&Bs[kk][tx * TN];
            *(float4*)&br[4] = *(const float4*)&Bs[kk][tx * TN + 4];
#pragma unroll
            for (int i = 0; i < TM; i++)
#pragma unroll
                for (int j = 0; j < TN; j++)
                    acc[i][j] += ar[i] * br[j];
        }
        __syncthreads();
    }

    // Epilogue
    const int nbase = n0 + tx * TN;
    const int b0    = nbase / HWSZ;
    const int hw0   = nbase - b0 * HWSZ;

#pragma unroll
    for (int i = 0; i < TM; i++) {
        const int m = m0 + ty * TM + i;
        if (MODE == 0) {
            const int   buf = m >> 9;           // 0=q 1=k 2=v (tile never straddles)
            const int   cc  = m & 511;
            const float scl = (buf == 0) ? 0.17677669529663687f : 1.0f; // 32^-0.5
            float* dst = (buf == 0) ? g_q : ((buf == 1) ? g_k : g_v);
#pragma unroll
            for (int j = 0; j < TN; j++) {
                int hw = hw0 + j, b = b0;
                if (hw >= HWSZ) { hw -= HWSZ; b++; }
                dst[(b * CHN + cc) * HWSZ + hw] = acc[i][j] * scl;
            }
        } else {
            const float bv = bias[m];
#pragma unroll
            for (int j = 0; j < TN; j++) {
                int hw = hw0 + j, b = b0;
                if (hw >= HWSZ) { hw -= HWSZ; b++; }
                Cout[(b * CHN + m) * HWSZ + hw] = acc[i][j] + bv;
            }
        }
    }
}

// ---------------------------------------------------------------------------
// Neighborhood attention. One thread per (token, head).
// Channel-major q/k/v so that adjacent-j lanes load adjacent addresses.
// Logits staged in smem (stride 49 words = 17 banks -> conflict-free).
// ---------------------------------------------------------------------------
__global__ __launch_bounds__(224)
void natten2d(const float* __restrict__ rpb)
{
    __shared__ float lsm[224 * 49];
    __shared__ float rpb_s[13 * 13];

    const int tx   = threadIdx.x;        // j: 0..55
    const int ty   = threadIdx.y;        // row within tile: 0..3
    const int tid  = ty * 56 + tx;
    const int head = blockIdx.y;
    const int b    = blockIdx.z;
    const int i    = blockIdx.x * 4 + ty;
    const int j    = tx;

    for (int idx = tid; idx < 169; idx += 224)
        rpb_s[idx] = rpb[head * 169 + idx];
    __syncthreads();

    const int bi = min(max(i - 3, 0), HH - KS);
    const int bj = min(max(j - 3, 0), WWD - KS);
    const int oi = bi - i + 6;           // 0..6
    const int oj = bj - j + 6;           // 0..6

    const int base = (b * CHN + head * DHEAD) * HWSZ;

    // q into registers (coalesced across j for each d)
    const float* qp = g_q + base + i * WWD + j;
    float qr[DHEAD];
#pragma unroll
    for (int d = 0; d < DHEAD; d++) qr[d] = qp[d * HWSZ];

    // ---- pass 1: logits ----
    const float* kp  = g_k + base;
    float* lrow = lsm + tid * 49;
    float mmax = -1e30f;
#pragma unroll 1
    for (int a = 0; a < KS; a++) {
        const float* ka   = kp + (bi + a) * WWD + bj;
        const float* bi_p = rpb_s + (oi + a) * 13 + oj;
#pragma unroll 1
        for (int c = 0; c < KS; c++) {
            const float* kk = ka + c;
            float s0 = 0.f, s1 = 0.f, s2 = 0.f, s3 = 0.f;
#pragma unroll
            for (int d = 0; d < DHEAD; d += 4) {
                s0 += qr[d + 0] * kk[(d + 0) * HWSZ];
                s1 += qr[d + 1] * kk[(d + 1) * HWSZ];
                s2 += qr[d + 2] * kk[(d + 2) * HWSZ];
                s3 += qr[d + 3] * kk[(d + 3) * HWSZ];
            }
            const float s = ((s0 + s1) + (s2 + s3)) + bi_p[c];
            lrow[a * KS + c] = s;
            mmax = fmaxf(mmax, s);
        }
    }

    // ---- softmax ----
    float ssum = 0.f;
#pragma unroll 1
    for (int t = 0; t < 49; t++) {
        const float e = __expf(lrow[t] - mmax);
        lrow[t] = e;
        ssum += e;
    }
    const float inv = __fdividef(1.f, ssum);

    // ---- pass 2: weighted V sum ----
    float oacc[DHEAD];
#pragma unroll
    for (int d = 0; d < DHEAD; d++) oacc[d] = 0.f;
    const float* vp = g_v + base;
#pragma unroll 1
    for (int a = 0; a < KS; a++) {
        const float* va = vp + (bi + a) * WWD + bj;
#pragma unroll 1
        for (int c = 0; c < KS; c++) {
            const float  w  = lrow[a * KS + c] * inv;
            const float* vv = va + c;
#pragma unroll
            for (int d = 0; d < DHEAD; d++)
                oacc[d] += w * vv[d * HWSZ];
        }
    }

    float* op = g_o + base + i * WWD + j;
#pragma unroll
    for (int d = 0; d < DHEAD; d++) op[d * HWSZ] = oacc[d];
}

// ---------------------------------------------------------------------------
extern "C" void kernel_launch(void* const* d_in, const int* in_sizes, int n_in,
                              void* d_out, int out_size)
{
    const float* x      = (const float*)d_in[0];  // (8,512,56,56)
    const float* qkv_w  = (const float*)d_in[1];  // (1536,512)
    const float* rpb    = (const float*)d_in[2];  // (16,13,13)
    const float* proj_w = (const float*)d_in[3];  // (512,512)
    const float* proj_b = (const float*)d_in[4];  // (512,)
    float* out = (float*)d_out;                   // (8,512,56,56)

    // 1) QKV projection: C[1536][25088], split into q(scaled)/k/v channel-major
    gemm_ct<0><<<dim3(NTOK / 128, 1536 / 128), 256>>>(qkv_w, x, nullptr, nullptr);

    // 2) Neighborhood attention -> g_o channel-major
    natten2d<<<dim3(HH / 4, NHEADS, BATCH), dim3(WWD, 4)>>>(rpb);

    // 3) Output projection + bias, written directly in NCHW
    gemm_ct<1><<<dim3(NTOK / 128, CHN / 128), 256>>>(proj_w, nullptr, proj_b, out);
}

// round 6
// speedup vs baseline: 1.0934x; 1.0934x over previous
#include <cuda_runtime.h>

// Problem constants (fixed by the reference)
#define BATCH   8
#define CHN     512
#define HH      56
#define WWD     56
#define HWSZ    3136            // 56*56
#define NHEADS  16
#define DHEAD   32
#define KS      7
#define NTOK    (BATCH*HWSZ)    // 25088

typedef unsigned long long ull;

__device__ __forceinline__ ull pack2(float lo, float hi) {
    ull r; asm("mov.b64 %0, {%1, %2};" : "=l"(r) : "f"(lo), "f"(hi)); return r;
}
__device__ __forceinline__ void ffma2(ull &d, ull a, ull b) {
    asm("fma.rn.f32x2 %0, %1, %2, %0;" : "+l"(d) : "l"(a), "l"(b));
}
__device__ __forceinline__ float2 unpack2(ull v) {
    float2 f; asm("mov.b64 {%0, %1}, %2;" : "=f"(f.x), "=f"(f.y) : "l"(v)); return f;
}

// Scratch: channel-major [b][c][hw] buffers (allocation-free per harness rules)
__device__ float g_q[BATCH*CHN*HWSZ];
__device__ float g_k[BATCH*CHN*HWSZ];
__device__ float g_v[BATCH*CHN*HWSZ];
__device__ float g_o[BATCH*CHN*HWSZ];

// ---------------------------------------------------------------------------
// GEMM: C[m][tok] = sum_k A[m][k] * B[k][tok]   (packed f32x2 FMA mainloop)
// MODE 0: A=qkv_w (M=1536), B=x, epilogue splits into g_q (scaled)/g_k/g_v
// MODE 1: A=proj_w (M=512), B=g_o, epilogue adds bias, writes NCHW output
// ---------------------------------------------------------------------------
template<int MODE>
__global__ __launch_bounds__(256, 2)
void gemm_ct(const float* __restrict__ A,
             const float* __restrict__ Bx,
             const float* __restrict__ bias,
             float* __restrict__ Cout)
{
    constexpr int BM = 128, BN = 128, BK = 16, TM = 8, TN = 8;
    __shared__ __align__(16) float As[BK][BM + 4];
    __shared__ __align__(16) float Bs[BK][BN + 4];

    const int tid = threadIdx.x;
    const int tx  = tid & 15;        // 16 N-threads
    const int ty  = tid >> 4;        // 16 M-threads
    const int m0  = blockIdx.y * BM;
    const int n0  = blockIdx.x * BN;

    const float* Bp = (MODE == 0) ? Bx : (const float*)g_o;

    // B loader: each thread owns one token column, 8 k-rows per tile
    const int tokl = tid & 127;
    const int tok  = n0 + tokl;
    const int bb   = tok / HWSZ;
    const int bhw  = tok - bb * HWSZ;
    const float* bptr = Bp + bb * (CHN * HWSZ) + bhw;
    const int bk0 = tid >> 7;        // 0 or 1

    // A loader: 128 rows x 16 k per tile -> 2 float4 per thread along K
    const int arow = tid >> 1;
    const int akq  = (tid & 1) << 3; // 0 or 8
    const float* aptr = A + (m0 + arow) * CHN + akq;

    ull acc2[TM][TN / 2];
#pragma unroll
    for (int i = 0; i < TM; i++)
#pragma unroll
        for (int j = 0; j < TN / 2; j++) acc2[i][j] = 0ULL;

    for (int k0 = 0; k0 < CHN; k0 += BK) {
        float4 a0 = *(const float4*)(aptr + k0);
        float4 a1 = *(const float4*)(aptr + k0 + 4);
        As[akq + 0][arow] = a0.x;  As[akq + 1][arow] = a0.y;
        As[akq + 2][arow] = a0.z;  As[akq + 3][arow] = a0.w;
        As[akq + 4][arow] = a1.x;  As[akq + 5][arow] = a1.y;
        As[akq + 6][arow] = a1.z;  As[akq + 7][arow] = a1.w;
#pragma unroll
        for (int p = 0; p < 8; p++) {
            const int kr = p * 2 + bk0;
            Bs[kr][tokl] = bptr[(k0 + kr) * HWSZ];
        }
        __syncthreads();
#pragma unroll
        for (int kk = 0; kk < BK; kk++) {
            float ar[TM];
            *(float4*)&ar[0] = *(const float4*)&As[kk][ty * TM];
            *(float4*)&ar[4] = *(const float4*)&As[kk][ty * TM + 4];
            const ull* bq = (const ull*)&Bs[kk][tx * TN];
            ull br2[4] = { bq[0], bq[1], bq[2], bq[3] };
            ull ar2[TM];
#pragma unroll
            for (int i = 0; i < TM; i++) ar2[i] = pack2(ar[i], ar[i]);
#pragma unroll
            for (int i = 0; i < TM; i++)
#pragma unroll
                for (int j = 0; j < TN / 2; j++)
                    ffma2(acc2[i][j], ar2[i], br2[j]);
        }
        __syncthreads();
    }

    // Epilogue
    const int nbase = n0 + tx * TN;
    const int b0    = nbase / HWSZ;
    const int hw0   = nbase - b0 * HWSZ;

#pragma unroll
    for (int i = 0; i < TM; i++) {
        const int m = m0 + ty * TM + i;
        float accv[TN];
#pragma unroll
        for (int j2 = 0; j2 < TN / 2; j2++) {
            float2 p = unpack2(acc2[i][j2]);
            accv[2 * j2]     = p.x;
            accv[2 * j2 + 1] = p.y;
        }
        if (MODE == 0) {
            const int   buf = m >> 9;           // 0=q 1=k 2=v (tile never straddles)
            const int   cc  = m & 511;
            const float scl = (buf == 0) ? 0.17677669529663687f : 1.0f; // 32^-0.5
            float* dst = (buf == 0) ? g_q : ((buf == 1) ? g_k : g_v);
#pragma unroll
            for (int j = 0; j < TN; j++) {
                int hw = hw0 + j, b = b0;
                if (hw >= HWSZ) { hw -= HWSZ; b++; }
                dst[(b * CHN + cc) * HWSZ + hw] = accv[j] * scl;
            }
        } else {
            const float bv = bias[m];
#pragma unroll
            for (int j = 0; j < TN; j++) {
                int hw = hw0 + j, b = b0;
                if (hw >= HWSZ) { hw -= HWSZ; b++; }
                Cout[(b * CHN + m) * HWSZ + hw] = accv[j] + bv;
            }
        }
    }
}

// ---------------------------------------------------------------------------
// Neighborhood attention, smem-tiled K/V.
// Block = 4 query rows x 56 cols (224 threads) for one (batch, head).
// The block's 4 rows need only K/V rows [rlo, rlo+9]; those are staged in
// smem in d-chunks of 8 with per-d planes (col contiguous -> conflict-free).
// Logits live in a fully-unrolled 49-register array.
// ---------------------------------------------------------------------------
#define DCH 8
#define TROWS 10
#define TPITCH 64

__global__ __launch_bounds__(224)
void natten2d(const float* __restrict__ rpb)
{
    __shared__ float kt[DCH * TROWS * TPITCH];   // 20 KB
    __shared__ float rpb_s[13 * 13];

    const int tx   = threadIdx.x;        // j: 0..55
    const int ty   = threadIdx.y;        // row within tile: 0..3
    const int tid  = ty * 56 + tx;
    const int head = blockIdx.y;
    const int b    = blockIdx.z;
    const int i0   = blockIdx.x * 4;
    const int i    = i0 + ty;
    const int j    = tx;

    for (int idx = tid; idx < 169; idx += 224)
        rpb_s[idx] = rpb[head * 169 + idx];
    __syncthreads();

    const int bi = min(max(i - 3, 0), HH - KS);
    const int bj = min(max(j - 3, 0), WWD - KS);
    const int oi = bi - i + 6;           // 0..6
    const int oj = bj - j + 6;           // 0..6

    const int rlo  = max(i0 - 3, 0);     // first tile row
    const int rowt = bi - rlo;           // this thread's first nbr row in tile

    const int base = (b * CHN + head * DHEAD) * HWSZ;
    const int poff = i * WWD + j;        // this thread's token within a plane

    // logits initialized with the relative-position bias
    float lg[49];
#pragma unroll
    for (int a = 0; a < KS; a++)
#pragma unroll
        for (int c = 0; c < KS; c++)
            lg[a * KS + c] = rpb_s[(oi + a) * 13 + (oj + c)];

    // ---- pass 1: logits over 4 d-chunks of K ----
#pragma unroll 1
    for (int ch = 0; ch < 4; ch++) {
        const int d0 = ch * DCH;
        __syncthreads();
        {
            const float* src = g_k + base + d0 * HWSZ;
            for (int idx = tid; idx < DCH * TROWS * 56; idx += 224) {
                const int d   = idx / (TROWS * 56);
                const int rem = idx - d * (TROWS * 56);
                const int r   = rem / 56;
                const int c   = rem - r * 56;
                const int gr  = min(rlo + r, HH - 1);
                kt[(d * TROWS + r) * TPITCH + c] = src[d * HWSZ + gr * WWD + c];
            }
        }
        __syncthreads();

        float qr[DCH];
#pragma unroll
        for (int d = 0; d < DCH; d++)
            qr[d] = g_q[base + (d0 + d) * HWSZ + poff];

#pragma unroll
        for (int a = 0; a < KS; a++) {
            const int rr = rowt + a;
#pragma unroll
            for (int c = 0; c < KS; c++) {
                float s = 0.f;
#pragma unroll
                for (int d = 0; d < DCH; d++)
                    s += qr[d] * kt[(d * TROWS + rr) * TPITCH + bj + c];
                lg[a * KS + c] += s;
            }
        }
    }

    // ---- softmax (registers) ----
    float mmax = lg[0];
#pragma unroll
    for (int t = 1; t < 49; t++) mmax = fmaxf(mmax, lg[t]);
    float ssum = 0.f;
#pragma unroll
    for (int t = 0; t < 49; t++) {
        const float e = __expf(lg[t] - mmax);
        lg[t] = e;
        ssum += e;
    }
    const float inv = __fdividef(1.f, ssum);
#pragma unroll
    for (int t = 0; t < 49; t++) lg[t] *= inv;

    // ---- pass 2: weighted V sum over 4 d-chunks ----
#pragma unroll 1
    for (int ch = 0; ch < 4; ch++) {
        const int d0 = ch * DCH;
        __syncthreads();
        {
            const float* src = g_v + base + d0 * HWSZ;
            for (int idx = tid; idx < DCH * TROWS * 56; idx += 224) {
                const int d   = idx / (TROWS * 56);
                const int rem = idx - d * (TROWS * 56);
                const int r   = rem / 56;
                const int c   = rem - r * 56;
                const int gr  = min(rlo + r, HH - 1);
                kt[(d * TROWS + r) * TPITCH + c] = src[d * HWSZ + gr * WWD + c];
            }
        }
        __syncthreads();

        float oa[DCH];
#pragma unroll
        for (int d = 0; d < DCH; d++) oa[d] = 0.f;

#pragma unroll
        for (int a = 0; a < KS; a++) {
            const int rr = rowt + a;
#pragma unroll
            for (int c = 0; c < KS; c++) {
                const float w = lg[a * KS + c];
#pragma unroll
                for (int d = 0; d < DCH; d++)
                    oa[d] += w * kt[(d * TROWS + rr) * TPITCH + bj + c];
            }
        }

#pragma unroll
        for (int d = 0; d < DCH; d++)
            g_o[base + (d0 + d) * HWSZ + poff] = oa[d];
    }
}

// ---------------------------------------------------------------------------
extern "C" void kernel_launch(void* const* d_in, const int* in_sizes, int n_in,
                              void* d_out, int out_size)
{
    const float* x      = (const float*)d_in[0];  // (8,512,56,56)
    const float* qkv_w  = (const float*)d_in[1];  // (1536,512)
    const float* rpb    = (const float*)d_in[2];  // (16,13,13)
    const float* proj_w = (const float*)d_in[3];  // (512,512)
    const float* proj_b = (const float*)d_in[4];  // (512,)
    float* out = (float*)d_out;                   // (8,512,56,56)

    // 1) QKV projection: C[1536][25088], split into q(scaled)/k/v channel-major
    gemm_ct<0><<<dim3(NTOK / 128, 1536 / 128), 256>>>(qkv_w, x, nullptr, nullptr);

    // 2) Neighborhood attention -> g_o channel-major
    natten2d<<<dim3(HH / 4, NHEADS, BATCH), dim3(WWD, 4)>>>(rpb);

    // 3) Output projection + bias, written directly in NCHW
    gemm_ct<1><<<dim3(NTOK / 128, CHN / 128), 256>>>(proj_w, nullptr, proj_b, out);
}